// round 1
// baseline (speedup 1.0000x reference)
#include <cuda_runtime.h>
#include <math.h>

#define NPTS    524288
#define NGRIDS  64
#define GVOX    262144      /* 64^3 */
#define DIN     164
#define NODES   64
#define PE_L    6

// Channel-interleaved feature volumes: [g][z][y][x] -> {c0, c1}
__device__ float2 g_packed[NGRIDS * GVOX];   // 128 MB static scratch

// ---------------- packed f32x2 helpers ----------------
__device__ __forceinline__ void fma2(unsigned long long& d,
                                     unsigned long long a,
                                     unsigned long long b) {
    asm("fma.rn.f32x2 %0, %1, %2, %0;" : "+l"(d) : "l"(a), "l"(b));
}
__device__ __forceinline__ unsigned long long bcast2(float f) {
    unsigned long long r;
    asm("mov.b64 %0, {%1, %2};" : "=l"(r) : "f"(f), "f"(f));
    return r;
}
__device__ __forceinline__ float2 unpack2(unsigned long long v) {
    float2 f;
    asm("mov.b64 {%0, %1}, %2;" : "=f"(f.x), "=f"(f.y) : "l"(v));
    return f;
}
__device__ __forceinline__ unsigned long long pack2(float a, float b) {
    unsigned long long r;
    asm("mov.b64 %0, {%1, %2};" : "=l"(r) : "f"(a), "f"(b));
    return r;
}

// acc[0..31] += f * row[0..63]   (row is 16B-aligned smem, contiguous 64 floats)
__device__ __forceinline__ void accum_row(unsigned long long* acc,
                                          const float* row, float f) {
    unsigned long long ff = bcast2(f);
    const ulonglong2* r2 = reinterpret_cast<const ulonglong2*>(row);
#pragma unroll
    for (int i = 0; i < 16; i++) {
        ulonglong2 w = r2[i];
        fma2(acc[2 * i], ff, w.x);
        fma2(acc[2 * i + 1], ff, w.y);
    }
}

// ---------------- repack: [g][c][v] f32 -> [g][v] float2 ----------------
__global__ void repack_kernel(const float* __restrict__ fg) {
    int idx = blockIdx.x * blockDim.x + threadIdx.x;       // 0 .. 16777215
    int g = idx >> 18;
    int v = idx & (GVOX - 1);
    float a = fg[(size_t)(2 * g) * GVOX + v];
    float b = fg[(size_t)(2 * g + 1) * GVOX + v];
    g_packed[idx] = make_float2(a, b);
}

// ---------------- smem layout (floats) ----------------
#define OFF_W0   0                       // 164*64 = 10496
#define OFF_W1T  (OFF_W0 + DIN * 64)     // 64*64  = 4096  (transposed: [k][j])
#define OFF_W2   (OFF_W1T + 64 * 64)     // 64
#define OFF_B1   (OFF_W2 + 64)           // 64
#define OFF_B0   (OFF_B1 + 64)           // 64
#define OFF_SC   (OFF_B0 + 64)           // 192
#define OFF_TR   (OFF_SC + 192)          // 192
#define SMEM_FLOATS (OFF_TR + 192)
#define SMEM_BYTES  (SMEM_FLOATS * 4)

__global__ void __launch_bounds__(256, 2)
amrsrn_main(const float* __restrict__ x,
            const float* __restrict__ gscale,
            const float* __restrict__ gtrans,
            const float* __restrict__ W0,
            const float* __restrict__ b0,
            const float* __restrict__ W1,
            const float* __restrict__ b1,
            const float* __restrict__ W2,
            const float* __restrict__ b2,
            float* __restrict__ out) {
    extern __shared__ float sm[];
    int tid = threadIdx.x;

    // ---- stage weights ----
    for (int i = tid; i < DIN * 64; i += 256) sm[OFF_W0 + i] = W0[i];
    for (int i = tid; i < 64 * 64; i += 256) {            // transpose W1 -> [k][j]
        int j = i >> 6, k = i & 63;
        sm[OFF_W1T + k * 64 + j] = W1[i];
    }
    for (int i = tid; i < 64; i += 256) {
        sm[OFF_W2 + i] = W2[i];
        sm[OFF_B1 + i] = b1[i];
        sm[OFF_B0 + i] = b0[i];
    }
    for (int i = tid; i < 192; i += 256) {
        sm[OFF_SC + i] = gscale[i];
        sm[OFF_TR + i] = gtrans[i];
    }
    __syncthreads();

    int pt = blockIdx.x * 256 + tid;
    float px = __ldg(&x[3 * pt + 0]);
    float py = __ldg(&x[3 * pt + 1]);
    float pz = __ldg(&x[3 * pt + 2]);
    float xyz[3] = {px, py, pz};

    // ---- h0 accumulators (32 packed f32x2), init = b0 ----
    unsigned long long acc[32];
    const unsigned long long* pb0 =
        reinterpret_cast<const unsigned long long*>(&sm[OFF_B0]);
#pragma unroll
    for (int i = 0; i < 32; i++) acc[i] = pb0[i];

    // ---- positional encoding into h0 ----
#pragma unroll 1
    for (int l = 0; l < PE_L; l++) {
        float freq = 3.14159265358979323846f * (float)(1 << l);
#pragma unroll
        for (int d = 0; d < 3; d++) {
            float s, c;
            sincosf(xyz[d] * freq, &s, &c);
            accum_row(acc, &sm[OFF_W0 + (l * 3 + d) * 64], s);
            accum_row(acc, &sm[OFF_W0 + (18 + l * 3 + d) * 64], c);
        }
    }

    // ---- grid samples into h0 ----
#pragma unroll 1
    for (int g = 0; g < NGRIDS; g++) {
        float sx = sm[OFF_SC + 3 * g + 0], sy = sm[OFF_SC + 3 * g + 1],
              sz = sm[OFF_SC + 3 * g + 2];
        float tx = sm[OFF_TR + 3 * g + 0], ty = sm[OFF_TR + 3 * g + 1],
              tz = sm[OFF_TR + 3 * g + 2];
        float ix = fmaf(fmaf(px, sx, tx), 31.5f, 31.5f);
        float iy = fmaf(fmaf(py, sy, ty), 31.5f, 31.5f);
        float iz = fmaf(fmaf(pz, sz, tz), 31.5f, 31.5f);

        if (ix > -1.f && ix < 64.f && iy > -1.f && iy < 64.f &&
            iz > -1.f && iz < 64.f) {
            float fx = floorf(ix), fy = floorf(iy), fz = floorf(iz);
            int X0 = (int)fx, Y0 = (int)fy, Z0 = (int)fz;
            float wx1 = ix - fx, wy1 = iy - fy, wz1 = iz - fz;
            float wx0 = 1.f - wx1, wy0 = 1.f - wy1, wz0 = 1.f - wz1;
            if (X0 < 0)   wx0 = 0.f;
            if (X0 >= 63) wx1 = 0.f;
            if (Y0 < 0)   wy0 = 0.f;
            if (Y0 >= 63) wy1 = 0.f;
            if (Z0 < 0)   wz0 = 0.f;
            if (Z0 >= 63) wz1 = 0.f;
            int x0c = max(X0, 0), x1c = min(X0 + 1, 63);
            int y0c = max(Y0, 0), y1c = min(Y0 + 1, 63);
            int z0c = max(Z0, 0), z1c = min(Z0 + 1, 63);

            const float2* vol = g_packed + ((size_t)g << 18);
            int b00 = (z0c << 12) + (y0c << 6);
            int b01 = (z0c << 12) + (y1c << 6);
            int b10 = (z1c << 12) + (y0c << 6);
            int b11 = (z1c << 12) + (y1c << 6);
            float2 v000 = __ldg(&vol[b00 + x0c]);
            float2 v001 = __ldg(&vol[b00 + x1c]);
            float2 v010 = __ldg(&vol[b01 + x0c]);
            float2 v011 = __ldg(&vol[b01 + x1c]);
            float2 v100 = __ldg(&vol[b10 + x0c]);
            float2 v101 = __ldg(&vol[b10 + x1c]);
            float2 v110 = __ldg(&vol[b11 + x0c]);
            float2 v111 = __ldg(&vol[b11 + x1c]);

            float w00 = wz0 * wy0, w01 = wz0 * wy1;
            float w10 = wz1 * wy0, w11 = wz1 * wy1;
            float c000 = w00 * wx0, c001 = w00 * wx1;
            float c010 = w01 * wx0, c011 = w01 * wx1;
            float c100 = w10 * wx0, c101 = w10 * wx1;
            float c110 = w11 * wx0, c111 = w11 * wx1;

            float f0 = c000 * v000.x, f1 = c000 * v000.y;
            f0 = fmaf(c001, v001.x, f0); f1 = fmaf(c001, v001.y, f1);
            f0 = fmaf(c010, v010.x, f0); f1 = fmaf(c010, v010.y, f1);
            f0 = fmaf(c011, v011.x, f0); f1 = fmaf(c011, v011.y, f1);
            f0 = fmaf(c100, v100.x, f0); f1 = fmaf(c100, v100.y, f1);
            f0 = fmaf(c101, v101.x, f0); f1 = fmaf(c101, v101.y, f1);
            f0 = fmaf(c110, v110.x, f0); f1 = fmaf(c110, v110.y, f1);
            f0 = fmaf(c111, v111.x, f0); f1 = fmaf(c111, v111.y, f1);

            accum_row(acc, &sm[OFF_W0 + (36 + 2 * g) * 64], f0);
            accum_row(acc, &sm[OFF_W0 + (37 + 2 * g) * 64], f1);
        }
    }

    // ---- snake activation on h0 (in place, stays packed) ----
#pragma unroll
    for (int i = 0; i < 32; i++) {
        float2 h = unpack2(acc[i]);
        float s0 = __sinf(h.x), s1 = __sinf(h.y);
        acc[i] = pack2(fmaf(0.5f, h.x, s0 * s0), fmaf(0.5f, h.y, s1 * s1));
    }

    // ---- layer1 (dot with transposed W1 rows) + snake + layer2 ----
    float outv = 0.f;
#pragma unroll 1
    for (int k = 0; k < 64; k++) {
        const ulonglong2* r2 =
            reinterpret_cast<const ulonglong2*>(&sm[OFF_W1T + k * 64]);
        unsigned long long a0 = 0ull, a1 = 0ull, a2 = 0ull, a3 = 0ull;
#pragma unroll
        for (int j = 0; j < 8; j++) {
            ulonglong2 wA = r2[2 * j];
            ulonglong2 wB = r2[2 * j + 1];
            fma2(a0, acc[4 * j + 0], wA.x);
            fma2(a1, acc[4 * j + 1], wA.y);
            fma2(a2, acc[4 * j + 2], wB.x);
            fma2(a3, acc[4 * j + 3], wB.y);
        }
        float2 fa = unpack2(a0), fb = unpack2(a1), fc = unpack2(a2),
               fd = unpack2(a3);
        float h = ((fa.x + fa.y) + (fb.x + fb.y)) +
                  ((fc.x + fc.y) + (fd.x + fd.y)) + sm[OFF_B1 + k];
        float s = __sinf(h);
        outv = fmaf(fmaf(0.5f, h, s * s), sm[OFF_W2 + k], outv);
    }

    out[pt] = outv + __ldg(b2);
}

extern "C" void kernel_launch(void* const* d_in, const int* in_sizes, int n_in,
                              void* d_out, int out_size) {
    const float* x      = (const float*)d_in[0];
    const float* gsc    = (const float*)d_in[1];
    const float* gtr    = (const float*)d_in[2];
    const float* fgrids = (const float*)d_in[3];
    const float* W0     = (const float*)d_in[4];
    const float* b0     = (const float*)d_in[5];
    const float* W1     = (const float*)d_in[6];
    const float* b1     = (const float*)d_in[7];
    const float* W2     = (const float*)d_in[8];
    const float* b2     = (const float*)d_in[9];
    float* out          = (float*)d_out;

    cudaFuncSetAttribute(amrsrn_main,
                         cudaFuncAttributeMaxDynamicSharedMemorySize,
                         SMEM_BYTES);

    repack_kernel<<<(NGRIDS * GVOX) / 256, 256>>>(fgrids);
    amrsrn_main<<<NPTS / 256, 256, SMEM_BYTES>>>(x, gsc, gtr, W0, b0, W1, b1,
                                                 W2, b2, out);
}